// round 10
// baseline (speedup 1.0000x reference)
#include <cuda_runtime.h>
#include <cstdint>

#define BDIM 128

// ---------------- packed-weight scratch (device globals; no allocation) ----------------
__device__ __align__(16) float g_W1[72 * 32];   // [j][i]: j<40 -> W_ih[i][j], else W_hh[i][j-40]
__device__ __align__(16) float g_F1[32 * 32];   // [j][i] = fc1_w[i][j]
__device__ __align__(16) float g_MW[32 * 32];   // [j][i] = mean_w[i][j]
__device__ __align__(16) float g_SW[32 * 32];   // [j][i] = std_w[i][j]
__device__ __align__(16) float g_b1[32];        // b_ih + b_hh
__device__ __align__(16) float g_fb[32];        // fc1_b
__device__ __align__(16) float g_mb[32];        // mean_b
__device__ __align__(16) float g_sb[32];        // std_b

__global__ void pack_kernel(const float* __restrict__ W_ih, const float* __restrict__ W_hh,
                            const float* __restrict__ b_ih, const float* __restrict__ b_hh,
                            const float* __restrict__ fc1_w, const float* __restrict__ fc1_b,
                            const float* __restrict__ mean_w, const float* __restrict__ mean_b,
                            const float* __restrict__ std_w, const float* __restrict__ std_b) {
    int t = threadIdx.x;
    for (int idx = t; idx < 72 * 32; idx += blockDim.x) {
        int j = idx >> 5, i = idx & 31;
        g_W1[idx] = (j < 40) ? W_ih[i * 40 + j] : W_hh[i * 32 + (j - 40)];
    }
    for (int idx = t; idx < 32 * 32; idx += blockDim.x) {
        int j = idx >> 5, i = idx & 31;
        g_F1[idx] = fc1_w[i * 32 + j];
        g_MW[idx] = mean_w[i * 32 + j];
        g_SW[idx] = std_w[i * 32 + j];
    }
    if (t < 32) {
        g_b1[t] = b_ih[t] + b_hh[t];
        g_fb[t] = fc1_b[t];
        g_mb[t] = mean_b[t];
        g_sb[t] = std_b[t];
    }
}

// ---------------- activations (fp32 intrinsics only, no asm) ----------------
__device__ __forceinline__ float fast_tanh(float x) {
    x = fminf(fmaxf(x, -15.f), 15.f);
    float e = __expf(2.f * x);                 // MUFU.EX2 chain
    return __fdividef(e - 1.f, e + 1.f);       // MUFU.RCP + mul
}
__device__ __forceinline__ float fast_elu(float x) {
    return x > 0.f ? x : (__expf(x) - 1.f);
}
__device__ __forceinline__ float softplus_eps(float x) {
    // softplus(x) = max(x,0) + log1p(exp(-|x|)); safe in both tails
    float ax = fabsf(x);
    return fmaxf(x, 0.f) + __logf(1.f + __expf(-ax)) + 1e-5f;
}

// Accumulate acc[4q..4q+3] += w * xj for q = 0..7 from a float4-vectorized weight column.
// All indices compile-time constant; arrays stay in registers.
#define DOT_COL(WV, base, xj)                              \
    do {                                                   \
        float _x = (xj);                                   \
        _Pragma("unroll")                                  \
        for (int q = 0; q < 8; q++) {                      \
            float4 w = (WV)[(base) * 8 + q];               \
            acc[4 * q + 0] = fmaf(w.x, _x, acc[4 * q + 0]);\
            acc[4 * q + 1] = fmaf(w.y, _x, acc[4 * q + 1]);\
            acc[4 * q + 2] = fmaf(w.z, _x, acc[4 * q + 2]);\
            acc[4 * q + 3] = fmaf(w.w, _x, acc[4 * q + 3]);\
        }                                                  \
    } while (0)

// ---------------- main rollout kernel: one thread per batch element ----------------
__global__ __launch_bounds__(BDIM, 1) void rssm_kernel(
    const float* __restrict__ s0, const float* __restrict__ h0,
    const float* __restrict__ actions, float* __restrict__ out,
    int B, int T, int nsteps)
{
    __shared__ __align__(16) float sW1[72 * 32];
    __shared__ __align__(16) float sF1[32 * 32];
    __shared__ __align__(16) float sMW[32 * 32];
    __shared__ __align__(16) float sSW[32 * 32];
    __shared__ __align__(16) float sb1[32];
    __shared__ __align__(16) float sfb[32];
    __shared__ __align__(16) float smb[32];
    __shared__ __align__(16) float ssb[32];

    {
        int t0 = threadIdx.x;
        for (int i = t0; i < 72 * 32; i += BDIM) sW1[i] = g_W1[i];
        for (int i = t0; i < 32 * 32; i += BDIM) {
            sF1[i] = g_F1[i];
            sMW[i] = g_MW[i];
            sSW[i] = g_SW[i];
        }
        if (t0 < 32) {
            sb1[t0] = g_b1[t0];
            sfb[t0] = g_fb[t0];
            smb[t0] = g_mb[t0];
            ssb[t0] = g_sb[t0];
        }
    }
    __syncthreads();

    int b = blockIdx.x * BDIM + threadIdx.x;
    if (b >= B) return;

    float s[32], h[32];
    {
        const float4* s4 = (const float4*)(s0 + (size_t)b * 32);
        const float4* h4 = (const float4*)(h0 + (size_t)b * 32);
#pragma unroll
        for (int q = 0; q < 8; q++) {
            float4 v = s4[q];
            s[4*q] = v.x; s[4*q+1] = v.y; s[4*q+2] = v.z; s[4*q+3] = v.w;
            float4 w = h4[q];
            h[4*q] = w.x; h[4*q+1] = w.y; h[4*q+2] = w.z; h[4*q+3] = w.w;
        }
    }

    const float4* act4 = (const float4*)(actions + (size_t)b * T * 8);
    float* outb = out + (size_t)b * 64;
    const float4* W1v = (const float4*)sW1;
    const float4* F1v = (const float4*)sF1;
    const float4* MWv = (const float4*)sMW;
    const float4* SWv = (const float4*)sSW;

#pragma unroll 1
    for (int t = 0; t < nsteps; t++) {
        float acc[32];

        // ---- GEMM1: h_pre[32] = W1 @ [s | a | h] + (b_ih + b_hh) ----
#pragma unroll
        for (int p = 0; p < 32; p++) acc[p] = sb1[p];
        {
            float4 a0 = act4[2 * t], a1 = act4[2 * t + 1];
#pragma unroll
            for (int j = 0; j < 32; j++) DOT_COL(W1v, j, s[j]);
            DOT_COL(W1v, 32, a0.x); DOT_COL(W1v, 33, a0.y);
            DOT_COL(W1v, 34, a0.z); DOT_COL(W1v, 35, a0.w);
            DOT_COL(W1v, 36, a1.x); DOT_COL(W1v, 37, a1.y);
            DOT_COL(W1v, 38, a1.z); DOT_COL(W1v, 39, a1.w);
#pragma unroll
            for (int j = 0; j < 32; j++) DOT_COL(W1v, 40 + j, h[j]);
        }
#pragma unroll
        for (int p = 0; p < 32; p++) h[p] = fast_tanh(acc[p]);
        // s[] is dead from here until the mean epilogue rewrites it.

        // ---- GEMM2: hid = elu(fc1 @ h + fc1_b) ----
#pragma unroll
        for (int p = 0; p < 32; p++) acc[p] = sfb[p];
#pragma unroll
        for (int j = 0; j < 32; j++) DOT_COL(F1v, j, h[j]);
        float hid[32];
#pragma unroll
        for (int p = 0; p < 32; p++) hid[p] = fast_elu(acc[p]);

        float4* o4 = (float4*)(outb + (size_t)t * B * 64);

        // ---- GEMM3a: mean = mean_w @ hid + mean_b; s <- mean; out[..0:32] ----
#pragma unroll
        for (int p = 0; p < 32; p++) acc[p] = smb[p];
#pragma unroll
        for (int j = 0; j < 32; j++) DOT_COL(MWv, j, hid[j]);
#pragma unroll
        for (int p = 0; p < 32; p++) s[p] = acc[p];
#pragma unroll
        for (int q = 0; q < 8; q++)
            o4[q] = make_float4(acc[4*q], acc[4*q+1], acc[4*q+2], acc[4*q+3]);

        // ---- GEMM3b: std = softplus(std_w @ hid + std_b) + 1e-5; out[..32:64] ----
#pragma unroll
        for (int p = 0; p < 32; p++) acc[p] = ssb[p];
#pragma unroll
        for (int j = 0; j < 32; j++) DOT_COL(SWv, j, hid[j]);
#pragma unroll
        for (int q = 0; q < 8; q++)
            o4[8 + q] = make_float4(softplus_eps(acc[4*q]),   softplus_eps(acc[4*q+1]),
                                    softplus_eps(acc[4*q+2]), softplus_eps(acc[4*q+3]));
    }
}

// ---------------- entry point ----------------
extern "C" void kernel_launch(void* const* d_in, const int* in_sizes, int n_in,
                              void* d_out, int out_size) {
    const float* s0      = (const float*)d_in[0];
    const float* h0      = (const float*)d_in[1];
    const float* actions = (const float*)d_in[2];
    const float* W_ih    = (const float*)d_in[3];
    const float* W_hh    = (const float*)d_in[4];
    const float* b_ih    = (const float*)d_in[5];
    const float* b_hh    = (const float*)d_in[6];
    const float* fc1_w   = (const float*)d_in[7];
    const float* fc1_b   = (const float*)d_in[8];
    const float* mean_w  = (const float*)d_in[9];
    const float* mean_b  = (const float*)d_in[10];
    const float* std_w   = (const float*)d_in[11];
    const float* std_b   = (const float*)d_in[12];
    // d_in[13] = horizon_length (device scalar); n_steps derivable from out_size.

    int B = in_sizes[0] / 32;                 // s0 is [B, 32]
    int T = in_sizes[2] / (B * 8);            // actions is [B, T, 8]
    int nsteps = out_size / (B * 64);         // out is [nsteps, B, 64]

    pack_kernel<<<1, 256>>>(W_ih, W_hh, b_ih, b_hh, fc1_w, fc1_b,
                            mean_w, mean_b, std_w, std_b);
    rssm_kernel<<<(B + BDIM - 1) / BDIM, BDIM>>>(s0, h0, actions, (float*)d_out,
                                                 B, T, nsteps);
}

// round 11
// speedup vs baseline: 1.0687x; 1.0687x over previous
#include <cuda_runtime.h>
#include <cstdint>

#define BDIM 128          // 32 batch elements per CTA, 4 threads per element

// ---------------- packed-weight scratch (device globals; no allocation) ----------------
__device__ __align__(16) float g_W1[72 * 32];   // [j][i]: j<40 -> W_ih[i][j], else W_hh[i][j-40]
__device__ __align__(16) float g_F1[32 * 32];   // [j][i] = fc1_w[i][j]
__device__ __align__(16) float g_MW[32 * 32];   // [j][i] = mean_w[i][j]
__device__ __align__(16) float g_SW[32 * 32];   // [j][i] = std_w[i][j]
__device__ __align__(16) float g_b1[32];        // b_ih + b_hh
__device__ __align__(16) float g_fb[32];        // fc1_b
__device__ __align__(16) float g_mb[32];        // mean_b
__device__ __align__(16) float g_sb[32];        // std_b

__global__ void pack_kernel(const float* __restrict__ W_ih, const float* __restrict__ W_hh,
                            const float* __restrict__ b_ih, const float* __restrict__ b_hh,
                            const float* __restrict__ fc1_w, const float* __restrict__ fc1_b,
                            const float* __restrict__ mean_w, const float* __restrict__ mean_b,
                            const float* __restrict__ std_w, const float* __restrict__ std_b) {
    int t = threadIdx.x;
    for (int idx = t; idx < 72 * 32; idx += blockDim.x) {
        int j = idx >> 5, i = idx & 31;
        g_W1[idx] = (j < 40) ? W_ih[i * 40 + j] : W_hh[i * 32 + (j - 40)];
    }
    for (int idx = t; idx < 32 * 32; idx += blockDim.x) {
        int j = idx >> 5, i = idx & 31;
        g_F1[idx] = fc1_w[i * 32 + j];
        g_MW[idx] = mean_w[i * 32 + j];
        g_SW[idx] = std_w[i * 32 + j];
    }
    if (t < 32) {
        g_b1[t] = b_ih[t] + b_hh[t];
        g_fb[t] = fc1_b[t];
        g_mb[t] = mean_b[t];
        g_sb[t] = std_b[t];
    }
}

// ---------------- activations (fp32 intrinsics only, no asm) ----------------
__device__ __forceinline__ float fast_tanh(float x) {
    x = fminf(fmaxf(x, -15.f), 15.f);
    float e = __expf(2.f * x);
    return __fdividef(e - 1.f, e + 1.f);
}
__device__ __forceinline__ float fast_elu(float x) {
    return x > 0.f ? x : (__expf(x) - 1.f);
}
__device__ __forceinline__ float softplus_eps(float x) {
    float ax = fabsf(x);
    return fmaxf(x, 0.f) + __logf(1.f + __expf(-ax)) + 1e-5f;
}

// width-4 broadcast within a 4-lane group
__device__ __forceinline__ float bcast4(float v, int src) {
    return __shfl_sync(0xffffffffu, v, src, 4);
}

// thread computes 8 outputs: column slice [c*8, c*8+8) of weight column `base`
#define DOT8(WV, base, xj)                                 \
    do {                                                   \
        float _x = (xj);                                   \
        float4 w0 = (WV)[(base) * 8 + c2];                 \
        float4 w1 = (WV)[(base) * 8 + c2 + 1];             \
        acc[0] = fmaf(w0.x, _x, acc[0]);                   \
        acc[1] = fmaf(w0.y, _x, acc[1]);                   \
        acc[2] = fmaf(w0.z, _x, acc[2]);                   \
        acc[3] = fmaf(w0.w, _x, acc[3]);                   \
        acc[4] = fmaf(w1.x, _x, acc[4]);                   \
        acc[5] = fmaf(w1.y, _x, acc[5]);                   \
        acc[6] = fmaf(w1.z, _x, acc[6]);                   \
        acc[7] = fmaf(w1.w, _x, acc[7]);                   \
    } while (0)

// fused mean+std pass: 16 accumulators, one shuffled x feeds both
#define DOT16MS(base, xj)                                  \
    do {                                                   \
        float _x = (xj);                                   \
        float4 m0 = MWv[(base) * 8 + c2];                  \
        float4 m1 = MWv[(base) * 8 + c2 + 1];              \
        float4 s0v = SWv[(base) * 8 + c2];                 \
        float4 s1v = SWv[(base) * 8 + c2 + 1];             \
        macc[0]  = fmaf(m0.x, _x, macc[0]);                \
        macc[1]  = fmaf(m0.y, _x, macc[1]);                \
        macc[2]  = fmaf(m0.z, _x, macc[2]);                \
        macc[3]  = fmaf(m0.w, _x, macc[3]);                \
        macc[4]  = fmaf(m1.x, _x, macc[4]);                \
        macc[5]  = fmaf(m1.y, _x, macc[5]);                \
        macc[6]  = fmaf(m1.z, _x, macc[6]);                \
        macc[7]  = fmaf(m1.w, _x, macc[7]);                \
        macc[8]  = fmaf(s0v.x, _x, macc[8]);               \
        macc[9]  = fmaf(s0v.y, _x, macc[9]);               \
        macc[10] = fmaf(s0v.z, _x, macc[10]);              \
        macc[11] = fmaf(s0v.w, _x, macc[11]);              \
        macc[12] = fmaf(s1v.x, _x, macc[12]);              \
        macc[13] = fmaf(s1v.y, _x, macc[13]);              \
        macc[14] = fmaf(s1v.z, _x, macc[14]);              \
        macc[15] = fmaf(s1v.w, _x, macc[15]);              \
    } while (0)

// ---------------- main rollout kernel: 4 threads per batch element ----------------
__global__ __launch_bounds__(BDIM) void rssm_kernel(
    const float* __restrict__ s0, const float* __restrict__ h0,
    const float* __restrict__ actions, float* __restrict__ out,
    int B, int T, int nsteps)
{
    __shared__ __align__(16) float sW1[72 * 32];
    __shared__ __align__(16) float sF1[32 * 32];
    __shared__ __align__(16) float sMW[32 * 32];
    __shared__ __align__(16) float sSW[32 * 32];
    __shared__ __align__(16) float sb1[32];
    __shared__ __align__(16) float sfb[32];
    __shared__ __align__(16) float smb[32];
    __shared__ __align__(16) float ssb[32];

    {
        int t0 = threadIdx.x;
        for (int i = t0; i < 72 * 32; i += BDIM) sW1[i] = g_W1[i];
        for (int i = t0; i < 32 * 32; i += BDIM) {
            sF1[i] = g_F1[i];
            sMW[i] = g_MW[i];
            sSW[i] = g_SW[i];
        }
        if (t0 < 32) {
            sb1[t0] = g_b1[t0];
            sfb[t0] = g_fb[t0];
            smb[t0] = g_mb[t0];
            ssb[t0] = g_sb[t0];
        }
    }
    __syncthreads();

    const int tid = threadIdx.x;
    const int c  = tid & 3;        // which 8-output slice this thread owns
    const int c2 = c * 2;          // float4 index of slice start
    const int e  = tid >> 2;       // element within CTA (0..31)
    const int b  = blockIdx.x * (BDIM / 4) + e;
    if (b >= B) return;

    const float4* W1v = (const float4*)sW1;
    const float4* F1v = (const float4*)sF1;
    const float4* MWv = (const float4*)sMW;
    const float4* SWv = (const float4*)sSW;
    const float4* sb1v = (const float4*)sb1;
    const float4* sfbv = (const float4*)sfb;
    const float4* smbv = (const float4*)smb;
    const float4* ssbv = (const float4*)ssb;

    // per-thread slices of state
    float s[8], h[8];
    {
        const float4* s4 = (const float4*)(s0 + (size_t)b * 32);
        const float4* h4 = (const float4*)(h0 + (size_t)b * 32);
        float4 v0 = s4[c2], v1 = s4[c2 + 1];
        s[0]=v0.x; s[1]=v0.y; s[2]=v0.z; s[3]=v0.w;
        s[4]=v1.x; s[5]=v1.y; s[6]=v1.z; s[7]=v1.w;
        float4 w0 = h4[c2], w1 = h4[c2 + 1];
        h[0]=w0.x; h[1]=w0.y; h[2]=w0.z; h[3]=w0.w;
        h[4]=w1.x; h[5]=w1.y; h[6]=w1.z; h[7]=w1.w;
    }

    const float4* act4 = (const float4*)(actions + (size_t)b * T * 8);
    float* outb = out + (size_t)b * 64;

#pragma unroll 1
    for (int t = 0; t < nsteps; t++) {
        float acc[8];

        // ---- GEMM1: h_pre = W1 @ [s | a | h] + (b_ih + b_hh) ----
        {
            float4 bv0 = sb1v[c2], bv1 = sb1v[c2 + 1];
            acc[0]=bv0.x; acc[1]=bv0.y; acc[2]=bv0.z; acc[3]=bv0.w;
            acc[4]=bv1.x; acc[5]=bv1.y; acc[6]=bv1.z; acc[7]=bv1.w;
        }
        {
            // all 4 group-threads load the full 8 actions (same address: broadcast)
            float4 a0 = act4[2 * t], a1 = act4[2 * t + 1];
#pragma unroll
            for (int j = 0; j < 32; j++) DOT8(W1v, j, bcast4(s[j & 7], j >> 3));
            DOT8(W1v, 32, a0.x); DOT8(W1v, 33, a0.y);
            DOT8(W1v, 34, a0.z); DOT8(W1v, 35, a0.w);
            DOT8(W1v, 36, a1.x); DOT8(W1v, 37, a1.y);
            DOT8(W1v, 38, a1.z); DOT8(W1v, 39, a1.w);
#pragma unroll
            for (int j = 0; j < 32; j++) DOT8(W1v, 40 + j, bcast4(h[j & 7], j >> 3));
        }
#pragma unroll
        for (int p = 0; p < 8; p++) h[p] = fast_tanh(acc[p]);

        // ---- GEMM2: hid = elu(fc1 @ h + fc1_b) ----
        {
            float4 bv0 = sfbv[c2], bv1 = sfbv[c2 + 1];
            acc[0]=bv0.x; acc[1]=bv0.y; acc[2]=bv0.z; acc[3]=bv0.w;
            acc[4]=bv1.x; acc[5]=bv1.y; acc[6]=bv1.z; acc[7]=bv1.w;
        }
#pragma unroll
        for (int j = 0; j < 32; j++) DOT8(F1v, j, bcast4(h[j & 7], j >> 3));
        float hid[8];
#pragma unroll
        for (int p = 0; p < 8; p++) hid[p] = fast_elu(acc[p]);

        // ---- GEMM3 (fused mean+std): one shuffle per j feeds 16 FMAs ----
        float macc[16];
        {
            float4 m0 = smbv[c2], m1 = smbv[c2 + 1];
            float4 q0 = ssbv[c2], q1 = ssbv[c2 + 1];
            macc[0]=m0.x;  macc[1]=m0.y;  macc[2]=m0.z;  macc[3]=m0.w;
            macc[4]=m1.x;  macc[5]=m1.y;  macc[6]=m1.z;  macc[7]=m1.w;
            macc[8]=q0.x;  macc[9]=q0.y;  macc[10]=q0.z; macc[11]=q0.w;
            macc[12]=q1.x; macc[13]=q1.y; macc[14]=q1.z; macc[15]=q1.w;
        }
#pragma unroll
        for (int j = 0; j < 32; j++) DOT16MS(j, bcast4(hid[j & 7], j >> 3));

        // ---- epilogue: s <- mean slice; out[t][b] = [mean | softplus(std)+eps] ----
        float4* o4 = (float4*)(outb + (size_t)t * B * 64);
        o4[c2]     = make_float4(macc[0], macc[1], macc[2], macc[3]);
        o4[c2 + 1] = make_float4(macc[4], macc[5], macc[6], macc[7]);
#pragma unroll
        for (int p = 0; p < 8; p++) s[p] = macc[p];
        o4[8 + c2]     = make_float4(softplus_eps(macc[8]),  softplus_eps(macc[9]),
                                     softplus_eps(macc[10]), softplus_eps(macc[11]));
        o4[8 + c2 + 1] = make_float4(softplus_eps(macc[12]), softplus_eps(macc[13]),
                                     softplus_eps(macc[14]), softplus_eps(macc[15]));
    }
}

// ---------------- entry point ----------------
extern "C" void kernel_launch(void* const* d_in, const int* in_sizes, int n_in,
                              void* d_out, int out_size) {
    const float* s0      = (const float*)d_in[0];
    const float* h0      = (const float*)d_in[1];
    const float* actions = (const float*)d_in[2];
    const float* W_ih    = (const float*)d_in[3];
    const float* W_hh    = (const float*)d_in[4];
    const float* b_ih    = (const float*)d_in[5];
    const float* b_hh    = (const float*)d_in[6];
    const float* fc1_w   = (const float*)d_in[7];
    const float* fc1_b   = (const float*)d_in[8];
    const float* mean_w  = (const float*)d_in[9];
    const float* mean_b  = (const float*)d_in[10];
    const float* std_w   = (const float*)d_in[11];
    const float* std_b   = (const float*)d_in[12];

    int B = in_sizes[0] / 32;                 // s0 is [B, 32]
    int T = in_sizes[2] / (B * 8);            // actions is [B, T, 8]
    int nsteps = out_size / (B * 64);         // out is [nsteps, B, 64]

    pack_kernel<<<1, 256>>>(W_ih, W_hh, b_ih, b_hh, fc1_w, fc1_b,
                            mean_w, mean_b, std_w, std_b);
    int elems_per_cta = BDIM / 4;
    rssm_kernel<<<(B + elems_per_cta - 1) / elems_per_cta, BDIM>>>(
        s0, h0, actions, (float*)d_out, B, T, nsteps);
}

// round 12
// speedup vs baseline: 1.7090x; 1.5992x over previous
#include <cuda_runtime.h>
#include <cstdint>

#define BDIM 128          // 32 element-groups per CTA × 4 threads; 2 elements per thread => 64 elems/CTA

// ---------------- packed-weight scratch (device globals; no allocation) ----------------
__device__ __align__(16) float g_W1[72 * 32];   // [j][i]: j<40 -> W_ih[i][j], else W_hh[i][j-40]
__device__ __align__(16) float g_F1[32 * 32];   // [j][i] = fc1_w[i][j]
__device__ __align__(16) float g_MW[32 * 32];   // [j][i] = mean_w[i][j]
__device__ __align__(16) float g_SW[32 * 32];   // [j][i] = std_w[i][j]
__device__ __align__(16) float g_b1[32];        // b_ih + b_hh
__device__ __align__(16) float g_fb[32];        // fc1_b
__device__ __align__(16) float g_mb[32];        // mean_b
__device__ __align__(16) float g_sb[32];        // std_b

__global__ void pack_kernel(const float* __restrict__ W_ih, const float* __restrict__ W_hh,
                            const float* __restrict__ b_ih, const float* __restrict__ b_hh,
                            const float* __restrict__ fc1_w, const float* __restrict__ fc1_b,
                            const float* __restrict__ mean_w, const float* __restrict__ mean_b,
                            const float* __restrict__ std_w, const float* __restrict__ std_b) {
    int t = threadIdx.x;
    for (int idx = t; idx < 72 * 32; idx += blockDim.x) {
        int j = idx >> 5, i = idx & 31;
        g_W1[idx] = (j < 40) ? W_ih[i * 40 + j] : W_hh[i * 32 + (j - 40)];
    }
    for (int idx = t; idx < 32 * 32; idx += blockDim.x) {
        int j = idx >> 5, i = idx & 31;
        g_F1[idx] = fc1_w[i * 32 + j];
        g_MW[idx] = mean_w[i * 32 + j];
        g_SW[idx] = std_w[i * 32 + j];
    }
    if (t < 32) {
        g_b1[t] = b_ih[t] + b_hh[t];
        g_fb[t] = fc1_b[t];
        g_mb[t] = mean_b[t];
        g_sb[t] = std_b[t];
    }
}

// ---------------- activations ----------------
__device__ __forceinline__ float fast_tanh(float x) {
    x = fminf(fmaxf(x, -15.f), 15.f);
    float e = __expf(2.f * x);
    return __fdividef(e - 1.f, e + 1.f);
}
__device__ __forceinline__ float fast_elu(float x) {
    return x > 0.f ? x : (__expf(x) - 1.f);
}
__device__ __forceinline__ float softplus_eps(float x) {
    float ax = fabsf(x);
    return fmaxf(x, 0.f) + __logf(1.f + __expf(-ax)) + 1e-5f;
}

// width-4 broadcast within a 4-lane group
__device__ __forceinline__ float bcast4(float v, int src) {
    return __shfl_sync(0xffffffffu, v, src, 4);
}

// one weight load pair serves BOTH elements: 2 LDS.128 -> 16 FMA
#define DOT8_2(WV, base, xA, xB)                            \
    do {                                                    \
        float _a = (xA), _b = (xB);                         \
        float4 w0 = (WV)[(base) * 8 + c2];                  \
        float4 w1 = (WV)[(base) * 8 + c2 + 1];              \
        accA[0] = fmaf(w0.x, _a, accA[0]);                  \
        accA[1] = fmaf(w0.y, _a, accA[1]);                  \
        accA[2] = fmaf(w0.z, _a, accA[2]);                  \
        accA[3] = fmaf(w0.w, _a, accA[3]);                  \
        accA[4] = fmaf(w1.x, _a, accA[4]);                  \
        accA[5] = fmaf(w1.y, _a, accA[5]);                  \
        accA[6] = fmaf(w1.z, _a, accA[6]);                  \
        accA[7] = fmaf(w1.w, _a, accA[7]);                  \
        accB[0] = fmaf(w0.x, _b, accB[0]);                  \
        accB[1] = fmaf(w0.y, _b, accB[1]);                  \
        accB[2] = fmaf(w0.z, _b, accB[2]);                  \
        accB[3] = fmaf(w0.w, _b, accB[3]);                  \
        accB[4] = fmaf(w1.x, _b, accB[4]);                  \
        accB[5] = fmaf(w1.y, _b, accB[5]);                  \
        accB[6] = fmaf(w1.z, _b, accB[6]);                  \
        accB[7] = fmaf(w1.w, _b, accB[7]);                  \
    } while (0)

// fused mean+std, both elements: 4 LDS.128 -> 32 FMA
#define DOT16MS_2(base, xA, xB)                             \
    do {                                                    \
        float _a = (xA), _b = (xB);                         \
        float4 m0 = MWv[(base) * 8 + c2];                   \
        float4 m1 = MWv[(base) * 8 + c2 + 1];               \
        float4 q0 = SWv[(base) * 8 + c2];                   \
        float4 q1 = SWv[(base) * 8 + c2 + 1];               \
        maccA[0]  = fmaf(m0.x, _a, maccA[0]);               \
        maccA[1]  = fmaf(m0.y, _a, maccA[1]);               \
        maccA[2]  = fmaf(m0.z, _a, maccA[2]);               \
        maccA[3]  = fmaf(m0.w, _a, maccA[3]);               \
        maccA[4]  = fmaf(m1.x, _a, maccA[4]);               \
        maccA[5]  = fmaf(m1.y, _a, maccA[5]);               \
        maccA[6]  = fmaf(m1.z, _a, maccA[6]);               \
        maccA[7]  = fmaf(m1.w, _a, maccA[7]);               \
        maccA[8]  = fmaf(q0.x, _a, maccA[8]);               \
        maccA[9]  = fmaf(q0.y, _a, maccA[9]);               \
        maccA[10] = fmaf(q0.z, _a, maccA[10]);              \
        maccA[11] = fmaf(q0.w, _a, maccA[11]);              \
        maccA[12] = fmaf(q1.x, _a, maccA[12]);              \
        maccA[13] = fmaf(q1.y, _a, maccA[13]);              \
        maccA[14] = fmaf(q1.z, _a, maccA[14]);              \
        maccA[15] = fmaf(q1.w, _a, maccA[15]);              \
        maccB[0]  = fmaf(m0.x, _b, maccB[0]);               \
        maccB[1]  = fmaf(m0.y, _b, maccB[1]);               \
        maccB[2]  = fmaf(m0.z, _b, maccB[2]);               \
        maccB[3]  = fmaf(m0.w, _b, maccB[3]);               \
        maccB[4]  = fmaf(m1.x, _b, maccB[4]);               \
        maccB[5]  = fmaf(m1.y, _b, maccB[5]);               \
        maccB[6]  = fmaf(m1.z, _b, maccB[6]);               \
        maccB[7]  = fmaf(m1.w, _b, maccB[7]);               \
        maccB[8]  = fmaf(q0.x, _b, maccB[8]);               \
        maccB[9]  = fmaf(q0.y, _b, maccB[9]);               \
        maccB[10] = fmaf(q0.z, _b, maccB[10]);              \
        maccB[11] = fmaf(q0.w, _b, maccB[11]);              \
        maccB[12] = fmaf(q1.x, _b, maccB[12]);              \
        maccB[13] = fmaf(q1.y, _b, maccB[13]);              \
        maccB[14] = fmaf(q1.z, _b, maccB[14]);              \
        maccB[15] = fmaf(q1.w, _b, maccB[15]);              \
    } while (0)

#define LOAD8(dst, src4, idx)                               \
    do {                                                    \
        float4 v0 = (src4)[idx], v1 = (src4)[(idx) + 1];    \
        dst[0]=v0.x; dst[1]=v0.y; dst[2]=v0.z; dst[3]=v0.w; \
        dst[4]=v1.x; dst[5]=v1.y; dst[6]=v1.z; dst[7]=v1.w; \
    } while (0)

// ---------------- main rollout kernel: 4 threads x 2 elements per thread ----------------
__global__ __launch_bounds__(BDIM) void rssm_kernel(
    const float* __restrict__ s0, const float* __restrict__ h0,
    const float* __restrict__ actions, float* __restrict__ out,
    int B, int T, int nsteps)
{
    __shared__ __align__(16) float sW1[72 * 32];
    __shared__ __align__(16) float sF1[32 * 32];
    __shared__ __align__(16) float sMW[32 * 32];
    __shared__ __align__(16) float sSW[32 * 32];
    __shared__ __align__(16) float sb1[32];
    __shared__ __align__(16) float sfb[32];
    __shared__ __align__(16) float smb[32];
    __shared__ __align__(16) float ssb[32];

    {
        int t0 = threadIdx.x;
        for (int i = t0; i < 72 * 32; i += BDIM) sW1[i] = g_W1[i];
        for (int i = t0; i < 32 * 32; i += BDIM) {
            sF1[i] = g_F1[i];
            sMW[i] = g_MW[i];
            sSW[i] = g_SW[i];
        }
        if (t0 < 32) {
            sb1[t0] = g_b1[t0];
            sfb[t0] = g_fb[t0];
            smb[t0] = g_mb[t0];
            ssb[t0] = g_sb[t0];
        }
    }
    __syncthreads();

    const int tid = threadIdx.x;
    const int c  = tid & 3;        // output-slice owner within 4-lane group
    const int c2 = c * 2;          // float4 index of slice start
    const int e  = tid >> 2;       // element-group within CTA (0..31)
    const int bA = blockIdx.x * (BDIM / 2) + e;        // element A
    const int bB = bA + 32;                            // element B
    if (bB >= B) return;           // B is a multiple of 64 in this problem

    const float4* W1v = (const float4*)sW1;
    const float4* F1v = (const float4*)sF1;
    const float4* MWv = (const float4*)sMW;
    const float4* SWv = (const float4*)sSW;
    const float4* sb1v = (const float4*)sb1;
    const float4* sfbv = (const float4*)sfb;
    const float4* smbv = (const float4*)smb;
    const float4* ssbv = (const float4*)ssb;

    float sA[8], hA[8], sB[8], hB[8];
    LOAD8(sA, ((const float4*)(s0 + (size_t)bA * 32)), c2);
    LOAD8(hA, ((const float4*)(h0 + (size_t)bA * 32)), c2);
    LOAD8(sB, ((const float4*)(s0 + (size_t)bB * 32)), c2);
    LOAD8(hB, ((const float4*)(h0 + (size_t)bB * 32)), c2);

    const float4* actA = (const float4*)(actions + (size_t)bA * T * 8);
    const float4* actB = (const float4*)(actions + (size_t)bB * T * 8);
    float* outA = out + (size_t)bA * 64;
    float* outB = out + (size_t)bB * 64;

#pragma unroll 1
    for (int t = 0; t < nsteps; t++) {
        float accA[8], accB[8];

        // ---- GEMM1: h_pre = W1 @ [s | a | h] + (b_ih + b_hh) ----
        {
            float4 bv0 = sb1v[c2], bv1 = sb1v[c2 + 1];
            accA[0]=bv0.x; accA[1]=bv0.y; accA[2]=bv0.z; accA[3]=bv0.w;
            accA[4]=bv1.x; accA[5]=bv1.y; accA[6]=bv1.z; accA[7]=bv1.w;
            accB[0]=bv0.x; accB[1]=bv0.y; accB[2]=bv0.z; accB[3]=bv0.w;
            accB[4]=bv1.x; accB[5]=bv1.y; accB[6]=bv1.z; accB[7]=bv1.w;
        }
        {
            float4 a0A = actA[2 * t], a1A = actA[2 * t + 1];
            float4 a0B = actB[2 * t], a1B = actB[2 * t + 1];
#pragma unroll
            for (int j = 0; j < 32; j++)
                DOT8_2(W1v, j, bcast4(sA[j & 7], j >> 3), bcast4(sB[j & 7], j >> 3));
            DOT8_2(W1v, 32, a0A.x, a0B.x); DOT8_2(W1v, 33, a0A.y, a0B.y);
            DOT8_2(W1v, 34, a0A.z, a0B.z); DOT8_2(W1v, 35, a0A.w, a0B.w);
            DOT8_2(W1v, 36, a1A.x, a1B.x); DOT8_2(W1v, 37, a1A.y, a1B.y);
            DOT8_2(W1v, 38, a1A.z, a1B.z); DOT8_2(W1v, 39, a1A.w, a1B.w);
#pragma unroll
            for (int j = 0; j < 32; j++)
                DOT8_2(W1v, 40 + j, bcast4(hA[j & 7], j >> 3), bcast4(hB[j & 7], j >> 3));
        }
#pragma unroll
        for (int p = 0; p < 8; p++) { hA[p] = fast_tanh(accA[p]); hB[p] = fast_tanh(accB[p]); }

        // ---- GEMM2: hid = elu(fc1 @ h + fc1_b) ----
        {
            float4 bv0 = sfbv[c2], bv1 = sfbv[c2 + 1];
            accA[0]=bv0.x; accA[1]=bv0.y; accA[2]=bv0.z; accA[3]=bv0.w;
            accA[4]=bv1.x; accA[5]=bv1.y; accA[6]=bv1.z; accA[7]=bv1.w;
            accB[0]=bv0.x; accB[1]=bv0.y; accB[2]=bv0.z; accB[3]=bv0.w;
            accB[4]=bv1.x; accB[5]=bv1.y; accB[6]=bv1.z; accB[7]=bv1.w;
        }
#pragma unroll
        for (int j = 0; j < 32; j++)
            DOT8_2(F1v, j, bcast4(hA[j & 7], j >> 3), bcast4(hB[j & 7], j >> 3));
        float hidA[8], hidB[8];
#pragma unroll
        for (int p = 0; p < 8; p++) { hidA[p] = fast_elu(accA[p]); hidB[p] = fast_elu(accB[p]); }

        // ---- GEMM3 (fused mean+std, both elements) ----
        float maccA[16], maccB[16];
        {
            float4 m0 = smbv[c2], m1 = smbv[c2 + 1];
            float4 q0 = ssbv[c2], q1 = ssbv[c2 + 1];
            maccA[0]=m0.x;  maccA[1]=m0.y;  maccA[2]=m0.z;  maccA[3]=m0.w;
            maccA[4]=m1.x;  maccA[5]=m1.y;  maccA[6]=m1.z;  maccA[7]=m1.w;
            maccA[8]=q0.x;  maccA[9]=q0.y;  maccA[10]=q0.z; maccA[11]=q0.w;
            maccA[12]=q1.x; maccA[13]=q1.y; maccA[14]=q1.z; maccA[15]=q1.w;
#pragma unroll
            for (int p = 0; p < 16; p++) maccB[p] = maccA[p];
        }
#pragma unroll
        for (int j = 0; j < 32; j++)
            DOT16MS_2(j, bcast4(hidA[j & 7], j >> 3), bcast4(hidB[j & 7], j >> 3));

        // ---- epilogue ----
        float4* o4A = (float4*)(outA + (size_t)t * B * 64);
        float4* o4B = (float4*)(outB + (size_t)t * B * 64);
        o4A[c2]     = make_float4(maccA[0], maccA[1], maccA[2], maccA[3]);
        o4A[c2 + 1] = make_float4(maccA[4], maccA[5], maccA[6], maccA[7]);
        o4B[c2]     = make_float4(maccB[0], maccB[1], maccB[2], maccB[3]);
        o4B[c2 + 1] = make_float4(maccB[4], maccB[5], maccB[6], maccB[7]);
#pragma unroll
        for (int p = 0; p < 8; p++) { sA[p] = maccA[p]; sB[p] = maccB[p]; }
        o4A[8 + c2]     = make_float4(softplus_eps(maccA[8]),  softplus_eps(maccA[9]),
                                      softplus_eps(maccA[10]), softplus_eps(maccA[11]));
        o4A[8 + c2 + 1] = make_float4(softplus_eps(maccA[12]), softplus_eps(maccA[13]),
                                      softplus_eps(maccA[14]), softplus_eps(maccA[15]));
        o4B[8 + c2]     = make_float4(softplus_eps(maccB[8]),  softplus_eps(maccB[9]),
                                      softplus_eps(maccB[10]), softplus_eps(maccB[11]));
        o4B[8 + c2 + 1] = make_float4(softplus_eps(maccB[12]), softplus_eps(maccB[13]),
                                      softplus_eps(maccB[14]), softplus_eps(maccB[15]));
    }
}

// ---------------- entry point ----------------
extern "C" void kernel_launch(void* const* d_in, const int* in_sizes, int n_in,
                              void* d_out, int out_size) {
    const float* s0      = (const float*)d_in[0];
    const float* h0      = (const float*)d_in[1];
    const float* actions = (const float*)d_in[2];
    const float* W_ih    = (const float*)d_in[3];
    const float* W_hh    = (const float*)d_in[4];
    const float* b_ih    = (const float*)d_in[5];
    const float* b_hh    = (const float*)d_in[6];
    const float* fc1_w   = (const float*)d_in[7];
    const float* fc1_b   = (const float*)d_in[8];
    const float* mean_w  = (const float*)d_in[9];
    const float* mean_b  = (const float*)d_in[10];
    const float* std_w   = (const float*)d_in[11];
    const float* std_b   = (const float*)d_in[12];

    int B = in_sizes[0] / 32;                 // s0 is [B, 32]
    int T = in_sizes[2] / (B * 8);            // actions is [B, T, 8]
    int nsteps = out_size / (B * 64);         // out is [nsteps, B, 64]

    pack_kernel<<<1, 256>>>(W_ih, W_hh, b_ih, b_hh, fc1_w, fc1_b,
                            mean_w, mean_b, std_w, std_b);
    int elems_per_cta = BDIM / 2;             // 4 threads/elem, 2 elems/thread
    rssm_kernel<<<(B + elems_per_cta - 1) / elems_per_cta, BDIM>>>(
        s0, h0, actions, (float*)d_out, B, T, nsteps);
}

// round 13
// speedup vs baseline: 2.0117x; 1.1771x over previous
#include <cuda_runtime.h>
#include <cstdint>

#define BDIM 128   // 16 element-groups × 8 threads; 4 elements/thread => 64 elems/CTA

// ---------------- packed-weight scratch (device globals; no allocation) ----------------
__device__ __align__(16) float g_W1[72 * 32];   // [j][i]: j<40 -> W_ih[i][j], else W_hh[i][j-40]
__device__ __align__(16) float g_F1[32 * 32];   // [j][i] = fc1_w[i][j]
__device__ __align__(16) float g_MW[32 * 32];   // [j][i] = mean_w[i][j]
__device__ __align__(16) float g_SW[32 * 32];   // [j][i] = std_w[i][j]
__device__ __align__(16) float g_b1[32];        // b_ih + b_hh
__device__ __align__(16) float g_fb[32];        // fc1_b
__device__ __align__(16) float g_mb[32];        // mean_b
__device__ __align__(16) float g_sb[32];        // std_b

__global__ void pack_kernel(const float* __restrict__ W_ih, const float* __restrict__ W_hh,
                            const float* __restrict__ b_ih, const float* __restrict__ b_hh,
                            const float* __restrict__ fc1_w, const float* __restrict__ fc1_b,
                            const float* __restrict__ mean_w, const float* __restrict__ mean_b,
                            const float* __restrict__ std_w, const float* __restrict__ std_b) {
    int t = threadIdx.x;
    for (int idx = t; idx < 72 * 32; idx += blockDim.x) {
        int j = idx >> 5, i = idx & 31;
        g_W1[idx] = (j < 40) ? W_ih[i * 40 + j] : W_hh[i * 32 + (j - 40)];
    }
    for (int idx = t; idx < 32 * 32; idx += blockDim.x) {
        int j = idx >> 5, i = idx & 31;
        g_F1[idx] = fc1_w[i * 32 + j];
        g_MW[idx] = mean_w[i * 32 + j];
        g_SW[idx] = std_w[i * 32 + j];
    }
    if (t < 32) {
        g_b1[t] = b_ih[t] + b_hh[t];
        g_fb[t] = fc1_b[t];
        g_mb[t] = mean_b[t];
        g_sb[t] = std_b[t];
    }
}

// ---------------- activations ----------------
__device__ __forceinline__ float fast_tanh(float x) {
    x = fminf(fmaxf(x, -15.f), 15.f);
    float e = __expf(2.f * x);
    return __fdividef(e - 1.f, e + 1.f);
}
__device__ __forceinline__ float fast_elu(float x) {
    return x > 0.f ? x : (__expf(x) - 1.f);
}
__device__ __forceinline__ float softplus_eps(float x) {
    float ax = fabsf(x);
    return fmaxf(x, 0.f) + __logf(1.f + __expf(-ax)) + 1e-5f;
}

// width-8 broadcast within an 8-lane group
__device__ __forceinline__ float bcast8(float v, int src) {
    return __shfl_sync(0xffffffffu, v, src, 8);
}

// one float4 weight load serves 4 outputs x 4 elements: 1 LDS.128 -> 16 FMA
#define DOT4X4(WV, base, xA, xB, xC, xD)                    \
    do {                                                    \
        float _xa = (xA), _xb = (xB), _xc = (xC), _xd = (xD); \
        float4 w = (WV)[(base) * 8 + c];                    \
        accA[0] = fmaf(w.x, _xa, accA[0]);                  \
        accA[1] = fmaf(w.y, _xa, accA[1]);                  \
        accA[2] = fmaf(w.z, _xa, accA[2]);                  \
        accA[3] = fmaf(w.w, _xa, accA[3]);                  \
        accB[0] = fmaf(w.x, _xb, accB[0]);                  \
        accB[1] = fmaf(w.y, _xb, accB[1]);                  \
        accB[2] = fmaf(w.z, _xb, accB[2]);                  \
        accB[3] = fmaf(w.w, _xb, accB[3]);                  \
        accC[0] = fmaf(w.x, _xc, accC[0]);                  \
        accC[1] = fmaf(w.y, _xc, accC[1]);                  \
        accC[2] = fmaf(w.z, _xc, accC[2]);                  \
        accC[3] = fmaf(w.w, _xc, accC[3]);                  \
        accD[0] = fmaf(w.x, _xd, accD[0]);                  \
        accD[1] = fmaf(w.y, _xd, accD[1]);                  \
        accD[2] = fmaf(w.z, _xd, accD[2]);                  \
        accD[3] = fmaf(w.w, _xd, accD[3]);                  \
    } while (0)

// fused mean+std: 2 LDS.128 -> 32 FMA (4 mean + 4 std outputs, 4 elements)
#define DOTMS(base, xA, xB, xC, xD)                         \
    do {                                                    \
        float _xa = (xA), _xb = (xB), _xc = (xC), _xd = (xD); \
        float4 m = MWv[(base) * 8 + c];                     \
        float4 q = SWv[(base) * 8 + c];                     \
        maccA[0] = fmaf(m.x, _xa, maccA[0]);                \
        maccA[1] = fmaf(m.y, _xa, maccA[1]);                \
        maccA[2] = fmaf(m.z, _xa, maccA[2]);                \
        maccA[3] = fmaf(m.w, _xa, maccA[3]);                \
        maccA[4] = fmaf(q.x, _xa, maccA[4]);                \
        maccA[5] = fmaf(q.y, _xa, maccA[5]);                \
        maccA[6] = fmaf(q.z, _xa, maccA[6]);                \
        maccA[7] = fmaf(q.w, _xa, maccA[7]);                \
        maccB[0] = fmaf(m.x, _xb, maccB[0]);                \
        maccB[1] = fmaf(m.y, _xb, maccB[1]);                \
        maccB[2] = fmaf(m.z, _xb, maccB[2]);                \
        maccB[3] = fmaf(m.w, _xb, maccB[3]);                \
        maccB[4] = fmaf(q.x, _xb, maccB[4]);                \
        maccB[5] = fmaf(q.y, _xb, maccB[5]);                \
        maccB[6] = fmaf(q.z, _xb, maccB[6]);                \
        maccB[7] = fmaf(q.w, _xb, maccB[7]);                \
        maccC[0] = fmaf(m.x, _xc, maccC[0]);                \
        maccC[1] = fmaf(m.y, _xc, maccC[1]);                \
        maccC[2] = fmaf(m.z, _xc, maccC[2]);                \
        maccC[3] = fmaf(m.w, _xc, maccC[3]);                \
        maccC[4] = fmaf(q.x, _xc, maccC[4]);                \
        maccC[5] = fmaf(q.y, _xc, maccC[5]);                \
        maccC[6] = fmaf(q.z, _xc, maccC[6]);                \
        maccC[7] = fmaf(q.w, _xc, maccC[7]);                \
        maccD[0] = fmaf(m.x, _xd, maccD[0]);                \
        maccD[1] = fmaf(m.y, _xd, maccD[1]);                \
        maccD[2] = fmaf(m.z, _xd, maccD[2]);                \
        maccD[3] = fmaf(m.w, _xd, maccD[3]);                \
        maccD[4] = fmaf(q.x, _xd, maccD[4]);                \
        maccD[5] = fmaf(q.y, _xd, maccD[5]);                \
        maccD[6] = fmaf(q.z, _xd, maccD[6]);                \
        maccD[7] = fmaf(q.w, _xd, maccD[7]);                \
    } while (0)

#define INIT4(dst, bv)  do { dst[0]=(bv).x; dst[1]=(bv).y; dst[2]=(bv).z; dst[3]=(bv).w; } while (0)
#define LOAD4(dst, ptr4) do { float4 _v = (ptr4)[c]; INIT4(dst, _v); } while (0)

// ---------------- main rollout kernel: 8 threads/elem x 4 elems/thread ----------------
__global__ __launch_bounds__(BDIM) void rssm_kernel(
    const float* __restrict__ s0, const float* __restrict__ h0,
    const float* __restrict__ actions, float* __restrict__ out,
    int B, int T, int nsteps)
{
    __shared__ __align__(16) float sW1[72 * 32];
    __shared__ __align__(16) float sF1[32 * 32];
    __shared__ __align__(16) float sMW[32 * 32];
    __shared__ __align__(16) float sSW[32 * 32];
    __shared__ __align__(16) float sb1[32];
    __shared__ __align__(16) float sfb[32];
    __shared__ __align__(16) float smb[32];
    __shared__ __align__(16) float ssb[32];

    {
        int t0 = threadIdx.x;
        for (int i = t0; i < 72 * 32; i += BDIM) sW1[i] = g_W1[i];
        for (int i = t0; i < 32 * 32; i += BDIM) {
            sF1[i] = g_F1[i];
            sMW[i] = g_MW[i];
            sSW[i] = g_SW[i];
        }
        if (t0 < 32) {
            sb1[t0] = g_b1[t0];
            sfb[t0] = g_fb[t0];
            smb[t0] = g_mb[t0];
            ssb[t0] = g_sb[t0];
        }
    }
    __syncthreads();

    const int tid = threadIdx.x;
    const int c = tid & 7;         // slice owner: outputs [4c, 4c+4)
    const int e = tid >> 3;        // element-group within CTA (0..15)
    const int bA = blockIdx.x * 64 + e;
    const int bB = bA + 16;
    const int bC = bA + 32;
    const int bD = bA + 48;
    if (bD >= B) return;           // B is a multiple of 64 here

    const float4* W1v = (const float4*)sW1;
    const float4* F1v = (const float4*)sF1;
    const float4* MWv = (const float4*)sMW;
    const float4* SWv = (const float4*)sSW;

    float sA[4], hA[4], sB[4], hB[4], sC[4], hC[4], sD[4], hD[4];
    LOAD4(sA, (const float4*)(s0 + (size_t)bA * 32));
    LOAD4(hA, (const float4*)(h0 + (size_t)bA * 32));
    LOAD4(sB, (const float4*)(s0 + (size_t)bB * 32));
    LOAD4(hB, (const float4*)(h0 + (size_t)bB * 32));
    LOAD4(sC, (const float4*)(s0 + (size_t)bC * 32));
    LOAD4(hC, (const float4*)(h0 + (size_t)bC * 32));
    LOAD4(sD, (const float4*)(s0 + (size_t)bD * 32));
    LOAD4(hD, (const float4*)(h0 + (size_t)bD * 32));

    const float4* actA = (const float4*)(actions + (size_t)bA * T * 8);
    const float4* actB = (const float4*)(actions + (size_t)bB * T * 8);
    const float4* actC = (const float4*)(actions + (size_t)bC * T * 8);
    const float4* actD = (const float4*)(actions + (size_t)bD * T * 8);
    float* outA = out + (size_t)bA * 64;
    float* outB = out + (size_t)bB * 64;
    float* outC = out + (size_t)bC * 64;
    float* outD = out + (size_t)bD * 64;

    const float4 b1v = ((const float4*)sb1)[c];
    const float4 fbv = ((const float4*)sfb)[c];
    const float4 mbv = ((const float4*)smb)[c];
    const float4 sbv = ((const float4*)ssb)[c];

#pragma unroll 1
    for (int t = 0; t < nsteps; t++) {
        float accA[4], accB[4], accC[4], accD[4];

        // ---- GEMM1: h_pre = W1 @ [s | a | h] + (b_ih + b_hh) ----
        INIT4(accA, b1v); INIT4(accB, b1v); INIT4(accC, b1v); INIT4(accD, b1v);
        {
            float4 a0A = actA[2 * t], a1A = actA[2 * t + 1];
            float4 a0B = actB[2 * t], a1B = actB[2 * t + 1];
            float4 a0C = actC[2 * t], a1C = actC[2 * t + 1];
            float4 a0D = actD[2 * t], a1D = actD[2 * t + 1];
#pragma unroll
            for (int j = 0; j < 32; j++)
                DOT4X4(W1v, j, bcast8(sA[j & 3], j >> 2), bcast8(sB[j & 3], j >> 2),
                               bcast8(sC[j & 3], j >> 2), bcast8(sD[j & 3], j >> 2));
            DOT4X4(W1v, 32, a0A.x, a0B.x, a0C.x, a0D.x);
            DOT4X4(W1v, 33, a0A.y, a0B.y, a0C.y, a0D.y);
            DOT4X4(W1v, 34, a0A.z, a0B.z, a0C.z, a0D.z);
            DOT4X4(W1v, 35, a0A.w, a0B.w, a0C.w, a0D.w);
            DOT4X4(W1v, 36, a1A.x, a1B.x, a1C.x, a1D.x);
            DOT4X4(W1v, 37, a1A.y, a1B.y, a1C.y, a1D.y);
            DOT4X4(W1v, 38, a1A.z, a1B.z, a1C.z, a1D.z);
            DOT4X4(W1v, 39, a1A.w, a1B.w, a1C.w, a1D.w);
#pragma unroll
            for (int j = 0; j < 32; j++)
                DOT4X4(W1v, 40 + j, bcast8(hA[j & 3], j >> 2), bcast8(hB[j & 3], j >> 2),
                                    bcast8(hC[j & 3], j >> 2), bcast8(hD[j & 3], j >> 2));
        }
#pragma unroll
        for (int p = 0; p < 4; p++) {
            hA[p] = fast_tanh(accA[p]); hB[p] = fast_tanh(accB[p]);
            hC[p] = fast_tanh(accC[p]); hD[p] = fast_tanh(accD[p]);
        }

        // ---- GEMM2: hid = elu(fc1 @ h + fc1_b) ----
        INIT4(accA, fbv); INIT4(accB, fbv); INIT4(accC, fbv); INIT4(accD, fbv);
#pragma unroll
        for (int j = 0; j < 32; j++)
            DOT4X4(F1v, j, bcast8(hA[j & 3], j >> 2), bcast8(hB[j & 3], j >> 2),
                           bcast8(hC[j & 3], j >> 2), bcast8(hD[j & 3], j >> 2));
        float hidA[4], hidB[4], hidC[4], hidD[4];
#pragma unroll
        for (int p = 0; p < 4; p++) {
            hidA[p] = fast_elu(accA[p]); hidB[p] = fast_elu(accB[p]);
            hidC[p] = fast_elu(accC[p]); hidD[p] = fast_elu(accD[p]);
        }

        // ---- GEMM3 (fused mean+std) ----
        float maccA[8], maccB[8], maccC[8], maccD[8];
        INIT4(maccA, mbv); INIT4(maccB, mbv); INIT4(maccC, mbv); INIT4(maccD, mbv);
        maccA[4]=sbv.x; maccA[5]=sbv.y; maccA[6]=sbv.z; maccA[7]=sbv.w;
        maccB[4]=sbv.x; maccB[5]=sbv.y; maccB[6]=sbv.z; maccB[7]=sbv.w;
        maccC[4]=sbv.x; maccC[5]=sbv.y; maccC[6]=sbv.z; maccC[7]=sbv.w;
        maccD[4]=sbv.x; maccD[5]=sbv.y; maccD[6]=sbv.z; maccD[7]=sbv.w;
#pragma unroll
        for (int j = 0; j < 32; j++)
            DOTMS(j, bcast8(hidA[j & 3], j >> 2), bcast8(hidB[j & 3], j >> 2),
                     bcast8(hidC[j & 3], j >> 2), bcast8(hidD[j & 3], j >> 2));

        // ---- epilogue: s <- mean slice; out[t][b] = [mean | softplus(std)+eps] ----
        float4* o4A = (float4*)(outA + (size_t)t * B * 64);
        float4* o4B = (float4*)(outB + (size_t)t * B * 64);
        float4* o4C = (float4*)(outC + (size_t)t * B * 64);
        float4* o4D = (float4*)(outD + (size_t)t * B * 64);
        o4A[c] = make_float4(maccA[0], maccA[1], maccA[2], maccA[3]);
        o4B[c] = make_float4(maccB[0], maccB[1], maccB[2], maccB[3]);
        o4C[c] = make_float4(maccC[0], maccC[1], maccC[2], maccC[3]);
        o4D[c] = make_float4(maccD[0], maccD[1], maccD[2], maccD[3]);
#pragma unroll
        for (int p = 0; p < 4; p++) {
            sA[p] = maccA[p]; sB[p] = maccB[p]; sC[p] = maccC[p]; sD[p] = maccD[p];
        }
        o4A[8 + c] = make_float4(softplus_eps(maccA[4]), softplus_eps(maccA[5]),
                                 softplus_eps(maccA[6]), softplus_eps(maccA[7]));
        o4B[8 + c] = make_float4(softplus_eps(maccB[4]), softplus_eps(maccB[5]),
                                 softplus_eps(maccB[6]), softplus_eps(maccB[7]));
        o4C[8 + c] = make_float4(softplus_eps(maccC[4]), softplus_eps(maccC[5]),
                                 softplus_eps(maccC[6]), softplus_eps(maccC[7]));
        o4D[8 + c] = make_float4(softplus_eps(maccD[4]), softplus_eps(maccD[5]),
                                 softplus_eps(maccD[6]), softplus_eps(maccD[7]));
    }
}

// ---------------- entry point ----------------
extern "C" void kernel_launch(void* const* d_in, const int* in_sizes, int n_in,
                              void* d_out, int out_size) {
    const float* s0      = (const float*)d_in[0];
    const float* h0      = (const float*)d_in[1];
    const float* actions = (const float*)d_in[2];
    const float* W_ih    = (const float*)d_in[3];
    const float* W_hh    = (const float*)d_in[4];
    const float* b_ih    = (const float*)d_in[5];
    const float* b_hh    = (const float*)d_in[6];
    const float* fc1_w   = (const float*)d_in[7];
    const float* fc1_b   = (const float*)d_in[8];
    const float* mean_w  = (const float*)d_in[9];
    const float* mean_b  = (const float*)d_in[10];
    const float* std_w   = (const float*)d_in[11];
    const float* std_b   = (const float*)d_in[12];

    int B = in_sizes[0] / 32;                 // s0 is [B, 32]
    int T = in_sizes[2] / (B * 8);            // actions is [B, T, 8]
    int nsteps = out_size / (B * 64);         // out is [nsteps, B, 64]

    pack_kernel<<<1, 256>>>(W_ih, W_hh, b_ih, b_hh, fc1_w, fc1_b,
                            mean_w, mean_b, std_w, std_b);
    int elems_per_cta = 64;                   // 8 threads/elem, 4 elems/thread
    rssm_kernel<<<(B + elems_per_cta - 1) / elems_per_cta, BDIM>>>(
        s0, h0, actions, (float*)d_out, B, T, nsteps);
}

// round 14
// speedup vs baseline: 2.4064x; 1.1962x over previous
#include <cuda_runtime.h>
#include <cstdint>

#define BDIM 128   // 16 element-groups × 8 threads; 4 elements/thread => 64 elems/CTA

// ---------------- packed-weight scratch (device globals; no allocation) ----------------
__device__ __align__(16) float g_W1[72 * 32];   // [j][i]: j<40 -> W_ih[i][j], else W_hh[i][j-40]
__device__ __align__(16) float g_F1[32 * 32];   // [j][i] = fc1_w[i][j]
__device__ __align__(16) float g_MW[32 * 32];   // [j][i] = mean_w[i][j]
__device__ __align__(16) float g_SW[32 * 32];   // [j][i] = std_w[i][j]
__device__ __align__(16) float g_b1[32];        // b_ih + b_hh
__device__ __align__(16) float g_fb[32];        // fc1_b
__device__ __align__(16) float g_mb[32];        // mean_b
__device__ __align__(16) float g_sb[32];        // std_b

__global__ void pack_kernel(const float* __restrict__ W_ih, const float* __restrict__ W_hh,
                            const float* __restrict__ b_ih, const float* __restrict__ b_hh,
                            const float* __restrict__ fc1_w, const float* __restrict__ fc1_b,
                            const float* __restrict__ mean_w, const float* __restrict__ mean_b,
                            const float* __restrict__ std_w, const float* __restrict__ std_b) {
    int t = threadIdx.x;
    for (int idx = t; idx < 72 * 32; idx += blockDim.x) {
        int j = idx >> 5, i = idx & 31;
        g_W1[idx] = (j < 40) ? W_ih[i * 40 + j] : W_hh[i * 32 + (j - 40)];
    }
    for (int idx = t; idx < 32 * 32; idx += blockDim.x) {
        int j = idx >> 5, i = idx & 31;
        g_F1[idx] = fc1_w[i * 32 + j];
        g_MW[idx] = mean_w[i * 32 + j];
        g_SW[idx] = std_w[i * 32 + j];
    }
    if (t < 32) {
        g_b1[t] = b_ih[t] + b_hh[t];
        g_fb[t] = fc1_b[t];
        g_mb[t] = mean_b[t];
        g_sb[t] = std_b[t];
    }
}

// ---------------- f32x2 helpers: by-value / named-scalar only (no address-taken arrays) ---
__device__ __forceinline__ unsigned long long pk(float x) {
    unsigned long long r;
    asm("mov.b64 %0, {%1, %1};" : "=l"(r) : "f"(x));
    return r;
}
__device__ __forceinline__ float2 up(unsigned long long v) {
    float2 f;
    asm("mov.b64 {%0, %1}, %2;" : "=f"(f.x), "=f"(f.y) : "l"(v));
    return f;
}
#define FMA2(acc, w, x) asm("fma.rn.f32x2 %0, %1, %2, %0;" : "+l"(acc) : "l"(w), "l"(x))

// ---------------- activations ----------------
__device__ __forceinline__ float fast_tanh(float x) {
    x = fminf(fmaxf(x, -15.f), 15.f);
    float e = __expf(2.f * x);
    return __fdividef(e - 1.f, e + 1.f);
}
__device__ __forceinline__ float fast_elu(float x) {
    return x > 0.f ? x : (__expf(x) - 1.f);
}
__device__ __forceinline__ float softplus_eps(float x) {
    float ax = fabsf(x);
    return fmaxf(x, 0.f) + __logf(1.f + __expf(-ax)) + 1e-5f;
}

// one ulonglong2 weight load (=LDS.128) -> 8 f32x2 FMA (4 outputs x 4 elements)
#define STEP4(Wu, jIdx, fA, fB, fC, fD)                      \
    do {                                                     \
        ulonglong2 _w = (Wu)[(jIdx) * 8 + c];                \
        unsigned long long _x;                               \
        _x = pk(fA); FMA2(a0A, _w.x, _x); FMA2(a1A, _w.y, _x); \
        _x = pk(fB); FMA2(a0B, _w.x, _x); FMA2(a1B, _w.y, _x); \
        _x = pk(fC); FMA2(a0C, _w.x, _x); FMA2(a1C, _w.y, _x); \
        _x = pk(fD); FMA2(a0D, _w.x, _x); FMA2(a1D, _w.y, _x); \
    } while (0)

// read 4 x-values per element from smem (broadcast LDS.128) and do 4 STEP4s
#define BLOCK4(Wu, jb, SV)                                   \
    do {                                                     \
        float4 _xA = (SV)[eA * 8 + (jb)];                    \
        float4 _xB = (SV)[eB * 8 + (jb)];                    \
        float4 _xC = (SV)[eC * 8 + (jb)];                    \
        float4 _xD = (SV)[eD * 8 + (jb)];                    \
        STEP4(Wu, (jb) * 4 + 0, _xA.x, _xB.x, _xC.x, _xD.x); \
        STEP4(Wu, (jb) * 4 + 1, _xA.y, _xB.y, _xC.y, _xD.y); \
        STEP4(Wu, (jb) * 4 + 2, _xA.z, _xB.z, _xC.z, _xD.z); \
        STEP4(Wu, (jb) * 4 + 3, _xA.w, _xB.w, _xC.w, _xD.w); \
    } while (0)

// fused mean+std: 2 weight loads -> 16 f32x2 FMA
#define STEPMS(jIdx, fA, fB, fC, fD)                         \
    do {                                                     \
        ulonglong2 _m = MWu[(jIdx) * 8 + c];                 \
        ulonglong2 _q = SWu[(jIdx) * 8 + c];                 \
        unsigned long long _x;                               \
        _x = pk(fA); FMA2(m0A, _m.x, _x); FMA2(m1A, _m.y, _x); FMA2(q0A, _q.x, _x); FMA2(q1A, _q.y, _x); \
        _x = pk(fB); FMA2(m0B, _m.x, _x); FMA2(m1B, _m.y, _x); FMA2(q0B, _q.x, _x); FMA2(q1B, _q.y, _x); \
        _x = pk(fC); FMA2(m0C, _m.x, _x); FMA2(m1C, _m.y, _x); FMA2(q0C, _q.x, _x); FMA2(q1C, _q.y, _x); \
        _x = pk(fD); FMA2(m0D, _m.x, _x); FMA2(m1D, _m.y, _x); FMA2(q0D, _q.x, _x); FMA2(q1D, _q.y, _x); \
    } while (0)

#define BLOCKMS(jb)                                          \
    do {                                                     \
        float4 _xA = sHidv[eA * 8 + (jb)];                   \
        float4 _xB = sHidv[eB * 8 + (jb)];                   \
        float4 _xC = sHidv[eC * 8 + (jb)];                   \
        float4 _xD = sHidv[eD * 8 + (jb)];                   \
        STEPMS((jb) * 4 + 0, _xA.x, _xB.x, _xC.x, _xD.x);    \
        STEPMS((jb) * 4 + 1, _xA.y, _xB.y, _xC.y, _xD.y);    \
        STEPMS((jb) * 4 + 2, _xA.z, _xB.z, _xC.z, _xD.z);    \
        STEPMS((jb) * 4 + 3, _xA.w, _xB.w, _xC.w, _xD.w);    \
    } while (0)

// ---------------- main rollout kernel: 8 threads/elem x 4 elems/thread, f32x2 engine ------
__global__ __launch_bounds__(BDIM) void rssm_kernel(
    const float* __restrict__ s0, const float* __restrict__ h0,
    const float* __restrict__ actions, float* __restrict__ out,
    int B, int T, int nsteps)
{
    __shared__ __align__(16) float sW1[72 * 32];
    __shared__ __align__(16) float sF1[32 * 32];
    __shared__ __align__(16) float sMW[32 * 32];
    __shared__ __align__(16) float sSW[32 * 32];
    __shared__ __align__(16) float sb1[32];
    __shared__ __align__(16) float sfb[32];
    __shared__ __align__(16) float smb[32];
    __shared__ __align__(16) float ssb[32];
    // per-element state: CTA-local element id 0..63, 32 floats each
    __shared__ __align__(16) float sS[64 * 32];
    __shared__ __align__(16) float sH[64 * 32];
    __shared__ __align__(16) float sHid[64 * 32];

    {
        int t0 = threadIdx.x;
        for (int i = t0; i < 72 * 32; i += BDIM) sW1[i] = g_W1[i];
        for (int i = t0; i < 32 * 32; i += BDIM) {
            sF1[i] = g_F1[i];
            sMW[i] = g_MW[i];
            sSW[i] = g_SW[i];
        }
        if (t0 < 32) {
            sb1[t0] = g_b1[t0];
            sfb[t0] = g_fb[t0];
            smb[t0] = g_mb[t0];
            ssb[t0] = g_sb[t0];
        }
    }

    const int tid = threadIdx.x;
    const int c  = tid & 7;        // slice owner: outputs [4c, 4c+4)
    const int e  = tid >> 3;       // element-group within CTA (0..15)
    const int eA = e, eB = e + 16, eC = e + 32, eD = e + 48;
    const int bA = blockIdx.x * 64 + e;
    const int bB = bA + 16, bC = bA + 32, bD = bA + 48;

    float4* sSv   = (float4*)sS;
    float4* sHv   = (float4*)sH;
    float4* sHidv = (float4*)sHid;

    // init per-element state into smem (each thread seeds its slice)
    if (bD < B) {
        sSv[eA * 8 + c] = ((const float4*)(s0 + (size_t)bA * 32))[c];
        sHv[eA * 8 + c] = ((const float4*)(h0 + (size_t)bA * 32))[c];
        sSv[eB * 8 + c] = ((const float4*)(s0 + (size_t)bB * 32))[c];
        sHv[eB * 8 + c] = ((const float4*)(h0 + (size_t)bB * 32))[c];
        sSv[eC * 8 + c] = ((const float4*)(s0 + (size_t)bC * 32))[c];
        sHv[eC * 8 + c] = ((const float4*)(h0 + (size_t)bC * 32))[c];
        sSv[eD * 8 + c] = ((const float4*)(s0 + (size_t)bD * 32))[c];
        sHv[eD * 8 + c] = ((const float4*)(h0 + (size_t)bD * 32))[c];
    }
    __syncthreads();
    if (bD >= B) return;

    const ulonglong2* W1u = (const ulonglong2*)sW1;
    const ulonglong2* F1u = (const ulonglong2*)sF1;
    const ulonglong2* MWu = (const ulonglong2*)sMW;
    const ulonglong2* SWu = (const ulonglong2*)sSW;
    const ulonglong2 b1u = ((const ulonglong2*)sb1)[c];
    const ulonglong2 fbu = ((const ulonglong2*)sfb)[c];
    const ulonglong2 mbu = ((const ulonglong2*)smb)[c];
    const ulonglong2 sbu = ((const ulonglong2*)ssb)[c];

    const float4* actA = (const float4*)(actions + (size_t)bA * T * 8);
    const float4* actB = (const float4*)(actions + (size_t)bB * T * 8);
    const float4* actC = (const float4*)(actions + (size_t)bC * T * 8);
    const float4* actD = (const float4*)(actions + (size_t)bD * T * 8);
    float* outA = out + (size_t)bA * 64;
    float* outB = out + (size_t)bB * 64;
    float* outC = out + (size_t)bC * 64;
    float* outD = out + (size_t)bD * 64;

#pragma unroll 1
    for (int t = 0; t < nsteps; t++) {
        // ================= GEMM1: h_pre = W1 @ [s | a | h] + b1 =================
        unsigned long long a0A = b1u.x, a1A = b1u.y;
        unsigned long long a0B = b1u.x, a1B = b1u.y;
        unsigned long long a0C = b1u.x, a1C = b1u.y;
        unsigned long long a0D = b1u.x, a1D = b1u.y;
        {
            float4 c0A = actA[2 * t], c1A = actA[2 * t + 1];
            float4 c0B = actB[2 * t], c1B = actB[2 * t + 1];
            float4 c0C = actC[2 * t], c1C = actC[2 * t + 1];
            float4 c0D = actD[2 * t], c1D = actD[2 * t + 1];
#pragma unroll
            for (int jb = 0; jb < 8; jb++) BLOCK4(W1u, jb, sSv);
            STEP4(W1u, 32, c0A.x, c0B.x, c0C.x, c0D.x);
            STEP4(W1u, 33, c0A.y, c0B.y, c0C.y, c0D.y);
            STEP4(W1u, 34, c0A.z, c0B.z, c0C.z, c0D.z);
            STEP4(W1u, 35, c0A.w, c0B.w, c0C.w, c0D.w);
            STEP4(W1u, 36, c1A.x, c1B.x, c1C.x, c1D.x);
            STEP4(W1u, 37, c1A.y, c1B.y, c1C.y, c1D.y);
            STEP4(W1u, 38, c1A.z, c1B.z, c1C.z, c1D.z);
            STEP4(W1u, 39, c1A.w, c1B.w, c1C.w, c1D.w);
#pragma unroll
            for (int jb = 0; jb < 8; jb++) BLOCK4(W1u + 40 * 8, jb, sHv);
        }
        __syncwarp();   // all GEMM1 reads of sS/sH done before overwriting sH
        {
            float2 vA0 = up(a0A), vA1 = up(a1A);
            float2 vB0 = up(a0B), vB1 = up(a1B);
            float2 vC0 = up(a0C), vC1 = up(a1C);
            float2 vD0 = up(a0D), vD1 = up(a1D);
            sHv[eA * 8 + c] = make_float4(fast_tanh(vA0.x), fast_tanh(vA0.y), fast_tanh(vA1.x), fast_tanh(vA1.y));
            sHv[eB * 8 + c] = make_float4(fast_tanh(vB0.x), fast_tanh(vB0.y), fast_tanh(vB1.x), fast_tanh(vB1.y));
            sHv[eC * 8 + c] = make_float4(fast_tanh(vC0.x), fast_tanh(vC0.y), fast_tanh(vC1.x), fast_tanh(vC1.y));
            sHv[eD * 8 + c] = make_float4(fast_tanh(vD0.x), fast_tanh(vD0.y), fast_tanh(vD1.x), fast_tanh(vD1.y));
        }
        __syncwarp();   // new h visible to group

        // ================= GEMM2: hid = elu(F1 @ h + fb) =================
        a0A = fbu.x; a1A = fbu.y; a0B = fbu.x; a1B = fbu.y;
        a0C = fbu.x; a1C = fbu.y; a0D = fbu.x; a1D = fbu.y;
#pragma unroll
        for (int jb = 0; jb < 8; jb++) BLOCK4(F1u, jb, sHv);
        {
            float2 vA0 = up(a0A), vA1 = up(a1A);
            float2 vB0 = up(a0B), vB1 = up(a1B);
            float2 vC0 = up(a0C), vC1 = up(a1C);
            float2 vD0 = up(a0D), vD1 = up(a1D);
            sHidv[eA * 8 + c] = make_float4(fast_elu(vA0.x), fast_elu(vA0.y), fast_elu(vA1.x), fast_elu(vA1.y));
            sHidv[eB * 8 + c] = make_float4(fast_elu(vB0.x), fast_elu(vB0.y), fast_elu(vB1.x), fast_elu(vB1.y));
            sHidv[eC * 8 + c] = make_float4(fast_elu(vC0.x), fast_elu(vC0.y), fast_elu(vC1.x), fast_elu(vC1.y));
            sHidv[eD * 8 + c] = make_float4(fast_elu(vD0.x), fast_elu(vD0.y), fast_elu(vD1.x), fast_elu(vD1.y));
        }
        __syncwarp();   // hid visible to group

        // ================= GEMM3: fused mean+std =================
        unsigned long long m0A = mbu.x, m1A = mbu.y, q0A = sbu.x, q1A = sbu.y;
        unsigned long long m0B = mbu.x, m1B = mbu.y, q0B = sbu.x, q1B = sbu.y;
        unsigned long long m0C = mbu.x, m1C = mbu.y, q0C = sbu.x, q1C = sbu.y;
        unsigned long long m0D = mbu.x, m1D = mbu.y, q0D = sbu.x, q1D = sbu.y;
#pragma unroll
        for (int jb = 0; jb < 8; jb++) BLOCKMS(jb);

        // ---- epilogue: s <- mean; out[t][b] = [mean | softplus(std)+eps] ----
        {
            float4* o4A = (float4*)(outA + (size_t)t * B * 64);
            float4* o4B = (float4*)(outB + (size_t)t * B * 64);
            float4* o4C = (float4*)(outC + (size_t)t * B * 64);
            float4* o4D = (float4*)(outD + (size_t)t * B * 64);
            float2 u0, u1;
            u0 = up(m0A); u1 = up(m1A);
            { float4 mv = make_float4(u0.x, u0.y, u1.x, u1.y); o4A[c] = mv; sSv[eA * 8 + c] = mv; }
            u0 = up(m0B); u1 = up(m1B);
            { float4 mv = make_float4(u0.x, u0.y, u1.x, u1.y); o4B[c] = mv; sSv[eB * 8 + c] = mv; }
            u0 = up(m0C); u1 = up(m1C);
            { float4 mv = make_float4(u0.x, u0.y, u1.x, u1.y); o4C[c] = mv; sSv[eC * 8 + c] = mv; }
            u0 = up(m0D); u1 = up(m1D);
            { float4 mv = make_float4(u0.x, u0.y, u1.x, u1.y); o4D[c] = mv; sSv[eD * 8 + c] = mv; }
            u0 = up(q0A); u1 = up(q1A);
            o4A[8 + c] = make_float4(softplus_eps(u0.x), softplus_eps(u0.y), softplus_eps(u1.x), softplus_eps(u1.y));
            u0 = up(q0B); u1 = up(q1B);
            o4B[8 + c] = make_float4(softplus_eps(u0.x), softplus_eps(u0.y), softplus_eps(u1.x), softplus_eps(u1.y));
            u0 = up(q0C); u1 = up(q1C);
            o4C[8 + c] = make_float4(softplus_eps(u0.x), softplus_eps(u0.y), softplus_eps(u1.x), softplus_eps(u1.y));
            u0 = up(q0D); u1 = up(q1D);
            o4D[8 + c] = make_float4(softplus_eps(u0.x), softplus_eps(u0.y), softplus_eps(u1.x), softplus_eps(u1.y));
        }
        __syncwarp();   // new s visible before next step's GEMM1
    }
}

// ---------------- entry point ----------------
extern "C" void kernel_launch(void* const* d_in, const int* in_sizes, int n_in,
                              void* d_out, int out_size) {
    const float* s0      = (const float*)d_in[0];
    const float* h0      = (const float*)d_in[1];
    const float* actions = (const float*)d_in[2];
    const float* W_ih    = (const float*)d_in[3];
    const float* W_hh    = (const float*)d_in[4];
    const float* b_ih    = (const float*)d_in[5];
    const float* b_hh    = (const float*)d_in[6];
    const float* fc1_w   = (const float*)d_in[7];
    const float* fc1_b   = (const float*)d_in[8];
    const float* mean_w  = (const float*)d_in[9];
    const float* mean_b  = (const float*)d_in[10];
    const float* std_w   = (const float*)d_in[11];
    const float* std_b   = (const float*)d_in[12];

    int B = in_sizes[0] / 32;                 // s0 is [B, 32]
    int T = in_sizes[2] / (B * 8);            // actions is [B, T, 8]
    int nsteps = out_size / (B * 64);         // out is [nsteps, B, 64]

    pack_kernel<<<1, 256>>>(W_ih, W_hh, b_ih, b_hh, fc1_w, fc1_b,
                            mean_w, mean_b, std_w, std_b);
    int elems_per_cta = 64;                   // 8 threads/elem, 4 elems/thread
    rssm_kernel<<<(B + elems_per_cta - 1) / elems_per_cta, BDIM>>>(
        s0, h0, actions, (float*)d_out, B, T, nsteps);
}